// round 6
// baseline (speedup 1.0000x reference)
#include <cuda_runtime.h>
#include <cuda_bf16.h>
#include <cuda_fp16.h>
#include <math.h>

// ---------------- constants ----------------
#define HDIM 128
#define GDIM 51
#define TPT  2048
#define RMAX 1.7330f
#define TAB_H   (RMAX / (float)(TPT - 1))
#define TAB_INVH ((float)(TPT - 1) / RMAX)
#define MAXN 100000

// ---------------- scratch ----------------
__device__ __align__(16) float  g_x1 [MAXN * HDIM];
__device__ __align__(16) float  g_agg[MAXN * HDIM];
__device__ __align__(16) float  g_t  [MAXN * HDIM];
__device__ __align__(16) __half g_tabh[TPT * HDIM];   // fp16 filter table
__device__ int g_is64;

__device__ __forceinline__ float sspf(float x) {
    float sp = fmaxf(x, 0.0f) + log1pf(__expf(-fabsf(x)));
    return sp - 0.6931471805599453f;
}

// ---------------- dtype sniff ----------------
__global__ void detect_kernel(const unsigned* __restrict__ ei, int E) {
    __shared__ unsigned red[256];
    unsigned acc = 0;
    int total = 2 * E;
    for (int i = threadIdx.x; i < 2048; i += 256) {
        long long w = 2LL * i + 1;
        if (w < total) acc |= ei[w];
    }
    red[threadIdx.x] = acc;
    __syncthreads();
    for (int s = 128; s > 0; s >>= 1) {
        if (threadIdx.x < s) red[threadIdx.x] |= red[threadIdx.x + s];
        __syncthreads();
    }
    if (threadIdx.x == 0) g_is64 = (red[0] == 0u) ? 1 : 0;
}

// ---------------- zero ----------------
__global__ void zero_kernel(int n4) {
    int i = blockIdx.x * blockDim.x + threadIdx.x;
    if (i < n4) ((float4*)g_agg)[i] = make_float4(0.f, 0.f, 0.f, 0.f);
}

// ---------------- filter table (fp16 output) ----------------
__global__ void table_kernel(const float* __restrict__ mlp0_w, const float* __restrict__ mlp0_b,
                             const float* __restrict__ mlp2_w, const float* __restrict__ mlp2_b) {
    __shared__ float ea[GDIM];
    __shared__ float hid[HDIM];
    const int f = threadIdx.x;
    const int p = blockIdx.x;
    const float ew = (float)p * TAB_H;

    if (f < GDIM) {
        float off = (float)f * 0.2f;
        float d = ew - off;
        ea[f] = expf(-12.5f * d * d);
    }
    __syncthreads();

    float a = mlp0_b[f];
    #pragma unroll
    for (int g = 0; g < GDIM; ++g)
        a = fmaf(ea[g], mlp0_w[f * GDIM + g], a);
    hid[f] = sspf(a);
    __syncthreads();

    float b = mlp2_b[f];
    #pragma unroll 8
    for (int k = 0; k < HDIM; ++k)
        b = fmaf(hid[k], mlp2_w[f * HDIM + k], b);

    float C = 0.5f * (cosf(ew * 0.31415926535897931f) + 1.0f);
    g_tabh[p * HDIM + f] = __float2half(b * C);
}

// ---------------- edge kernel: fp16 table, 1.5KB L2 traffic/edge ----------------
__global__ __launch_bounds__(256) void edge_kernel(const void* __restrict__ ei_raw,
                                                   const float* __restrict__ pos, int E) {
    const int lane = threadIdx.x & 31;
    const int warp = threadIdx.x >> 5;
    const int base = (blockIdx.x * 8 + warp) * 32;
    if (base >= E) return;

    const int is64 = g_is64;

    int r = 0, c = 0, i0 = 0; float fr = 0.f;
    const int e = base + lane;
    if (e < E) {
        if (is64) {
            const long long* ei = (const long long*)ei_raw;
            r = (int)ei[e];
            c = (int)ei[(size_t)E + e];
        } else {
            const int* ei = (const int*)ei_raw;
            r = ei[e];
            c = ei[(size_t)E + e];
        }
        float ax = __ldg(pos + 3 * r), ay = __ldg(pos + 3 * r + 1), az = __ldg(pos + 3 * r + 2);
        float bx = __ldg(pos + 3 * c), by = __ldg(pos + 3 * c + 1), bz = __ldg(pos + 3 * c + 2);
        float dx = ax - bx, dy = ay - by, dz = az - bz;
        float ew = sqrtf(fmaf(dx, dx, fmaf(dy, dy, fmaf(dz, dz, 1e-12f))));
        float t = ew * TAB_INVH;
        i0 = (int)t;
        if (i0 > TPT - 2) i0 = TPT - 2;
        fr = t - (float)i0;
    }

    const uint2* T = (const uint2*)g_tabh;   // 4 halfs per uint2; 32 lanes cover 128 cols

    int nv = E - base; if (nv > 32) nv = 32;
    for (int j = 0; j < nv; ++j) {
        int   rr = __shfl_sync(0xffffffffu, r,  j);
        int   cc = __shfl_sync(0xffffffffu, c,  j);
        int   ii = __shfl_sync(0xffffffffu, i0, j);
        float ff = __shfl_sync(0xffffffffu, fr, j);

        float4 xv = __ldg((const float4*)g_x1 + (size_t)rr * 32 + lane);
        uint2 a0 = __ldg(T + (size_t)ii * 32 + lane);
        uint2 a1 = __ldg(T + (size_t)(ii + 1) * 32 + lane);

        float2 p0 = __half22float2(*(__half2*)&a0.x);
        float2 p1 = __half22float2(*(__half2*)&a0.y);
        float2 q0 = __half22float2(*(__half2*)&a1.x);
        float2 q1 = __half22float2(*(__half2*)&a1.y);

        float wx = fmaf(ff, q0.x - p0.x, p0.x);
        float wy = fmaf(ff, q0.y - p0.y, p0.y);
        float wz = fmaf(ff, q1.x - p1.x, p1.x);
        float ww = fmaf(ff, q1.y - p1.y, p1.y);

        float m0 = xv.x * wx, m1 = xv.y * wy, m2 = xv.z * wz, m3 = xv.w * ww;

        float* p = g_agg + (size_t)cc * HDIM + lane * 4;
        asm volatile("red.global.add.v4.f32 [%0], {%1, %2, %3, %4};"
                     :: "l"(p), "f"(m0), "f"(m1), "f"(m2), "f"(m3) : "memory");
    }
}

// ---------------- GEMM: [n,128] @ W[128,128]^T, fused epilogue ----------------
// W in smem (permuted, conflict-free LDS.128), X staged through smem in 32-k
// chunks with a 2-stage cp.async pipeline. 2 CTAs/SM. FFMA2 accumulators.
#define XCHUNK 32
#define GEMM_SMEM ((128 * 128 + 2 * 128 * XCHUNK) * 4)   // 64KB W + 32KB X

__device__ __forceinline__ void cp16(float* s, const float4* g) {
    unsigned sa = (unsigned)__cvta_generic_to_shared(s);
    asm volatile("cp.async.cg.shared.global [%0], [%1], 16;" :: "r"(sa), "l"(g));
}

__global__ __launch_bounds__(256, 2) void gemm128_kernel(
    const float* __restrict__ X, const float* __restrict__ W,
    const float* __restrict__ bias, const float* __restrict__ res,
    float* __restrict__ Y, int n, int flags)
{
    extern __shared__ float sm[];
    float* ws = sm;                         // permuted [k][128]
    float* xs = sm + 128 * 128;             // [2][128][32]

    const int tid  = threadIdx.x;
    const int row0 = blockIdx.x << 7;
    const float4* X4 = (const float4*)X;

    // ---- stage W (one-time): load float4 along k, scatter into permuted layout ----
    #pragma unroll
    for (int it = 0; it < 16; ++it) {
        int idx = tid + it * 256;
        int o = idx & 127, kq = idx >> 7;
        float4 v = __ldg((const float4*)W + o * 32 + kq);
        int t = o >> 3, half = (o >> 2) & 1, j = o & 3;
        int base = half * 64 + t * 4 + j;
        ws[(kq * 4 + 0) * 128 + base] = v.x;
        ws[(kq * 4 + 1) * 128 + base] = v.y;
        ws[(kq * 4 + 2) * 128 + base] = v.z;
        ws[(kq * 4 + 3) * 128 + base] = v.w;
    }

    // ---- X stage loader: chunk cb (32 k) into stage s ----
    auto stage_load = [&](int s, int cb) {
        float* dst = xs + s * 128 * XCHUNK;
        #pragma unroll
        for (int it = 0; it < 4; ++it) {
            int idx = tid + it * 256;        // 0..1023 float4s
            int r = idx >> 3, kq = idx & 7;  // kq: float4 within 32k
            int gr = row0 + r; if (gr > n - 1) gr = n - 1;
            cp16(dst + r * XCHUNK + kq * 4, X4 + (size_t)gr * 32 + cb * 8 + kq);
        }
        asm volatile("cp.async.commit_group;" ::: "memory");
    };

    const int tx = tid & 15, ty = tid >> 4;

    unsigned long long acc[8][4];
    #pragma unroll
    for (int i = 0; i < 8; ++i)
        #pragma unroll
        for (int m = 0; m < 4; ++m) acc[i][m] = 0ull;

    stage_load(0, 0);

    #pragma unroll
    for (int cb = 0; cb < 4; ++cb) {
        if (cb < 3) {
            stage_load((cb + 1) & 1, cb + 1);
            asm volatile("cp.async.wait_group 1;" ::: "memory");
        } else {
            asm volatile("cp.async.wait_group 0;" ::: "memory");
        }
        __syncthreads();

        const float* xb = xs + (cb & 1) * 128 * XCHUNK;
        #pragma unroll
        for (int k4 = 0; k4 < 8; ++k4) {
            float4 xv[8];
            #pragma unroll
            for (int i = 0; i < 8; ++i)
                xv[i] = *(const float4*)(xb + (ty * 8 + i) * XCHUNK + k4 * 4);

            #pragma unroll
            for (int dk = 0; dk < 4; ++dk) {
                const int k = cb * 32 + k4 * 4 + dk;
                ulonglong2 wa = *(const ulonglong2*)(ws + (k << 7) + (tx << 2));
                ulonglong2 wb = *(const ulonglong2*)(ws + (k << 7) + 64 + (tx << 2));
                #pragma unroll
                for (int i = 0; i < 8; ++i) {
                    float xsv = (dk == 0) ? xv[i].x : (dk == 1) ? xv[i].y
                              : (dk == 2) ? xv[i].z : xv[i].w;
                    unsigned xu = __float_as_uint(xsv);
                    unsigned long long x2;
                    asm("mov.b64 %0, {%1, %1};" : "=l"(x2) : "r"(xu));
                    asm("fma.rn.f32x2 %0, %1, %2, %0;" : "+l"(acc[i][0]) : "l"(x2), "l"(wa.x));
                    asm("fma.rn.f32x2 %0, %1, %2, %0;" : "+l"(acc[i][1]) : "l"(x2), "l"(wa.y));
                    asm("fma.rn.f32x2 %0, %1, %2, %0;" : "+l"(acc[i][2]) : "l"(x2), "l"(wb.x));
                    asm("fma.rn.f32x2 %0, %1, %2, %0;" : "+l"(acc[i][3]) : "l"(x2), "l"(wb.y));
                }
            }
        }
        __syncthreads();
    }

    // ---- epilogue: thread owns cols [8tx .. 8tx+7] ----
    const int col = tx << 3;
    float4 b0 = make_float4(0.f, 0.f, 0.f, 0.f), b1 = b0;
    if (bias) {
        b0 = __ldg((const float4*)bias + tx * 2);
        b1 = __ldg((const float4*)bias + tx * 2 + 1);
    }
    #pragma unroll
    for (int i = 0; i < 8; ++i) {
        int r = row0 + ty * 8 + i;
        if (r >= n) continue;
        float2 p0 = *(float2*)&acc[i][0];
        float2 p1 = *(float2*)&acc[i][1];
        float2 p2 = *(float2*)&acc[i][2];
        float2 p3 = *(float2*)&acc[i][3];
        float4 v0 = make_float4(p0.x + b0.x, p0.y + b0.y, p1.x + b0.z, p1.y + b0.w);
        float4 v1 = make_float4(p2.x + b1.x, p2.y + b1.y, p3.x + b1.z, p3.y + b1.w);
        if (flags & 1) {
            v0.x = sspf(v0.x); v0.y = sspf(v0.y); v0.z = sspf(v0.z); v0.w = sspf(v0.w);
            v1.x = sspf(v1.x); v1.y = sspf(v1.y); v1.z = sspf(v1.z); v1.w = sspf(v1.w);
        }
        if (flags & 2) {
            float4 r0 = __ldg((const float4*)(res + (size_t)r * HDIM + col));
            float4 r1 = __ldg((const float4*)(res + (size_t)r * HDIM + col + 4));
            v0.x += r0.x; v0.y += r0.y; v0.z += r0.z; v0.w += r0.w;
            v1.x += r1.x; v1.y += r1.y; v1.z += r1.z; v1.w += r1.w;
        }
        *(float4*)(Y + (size_t)r * HDIM + col)     = v0;
        *(float4*)(Y + (size_t)r * HDIM + col + 4) = v1;
    }
}

// ---------------- launch ----------------
extern "C" void kernel_launch(void* const* d_in, const int* in_sizes, int n_in,
                              void* d_out, int out_size) {
    const float* z      = (const float*)d_in[0];
    const float* pos    = (const float*)d_in[1];
    const void*  ei     = d_in[2];
    const float* lin1_w = (const float*)d_in[3];
    const float* lin2_w = (const float*)d_in[4];
    const float* lin2_b = (const float*)d_in[5];
    const float* mlp0_w = (const float*)d_in[6];
    const float* mlp0_b = (const float*)d_in[7];
    const float* mlp2_w = (const float*)d_in[8];
    const float* mlp2_b = (const float*)d_in[9];
    const float* blk_w  = (const float*)d_in[10];
    const float* blk_b  = (const float*)d_in[11];
    const float* out1_w = (const float*)d_in[12];
    const float* out1_b = (const float*)d_in[13];
    const float* out2_w = (const float*)d_in[14];
    const float* out2_b = (const float*)d_in[15];
    float* out = (float*)d_out;

    const int n = in_sizes[0] / HDIM;
    const int E = in_sizes[2] / 2;

    float *x1p, *aggp, *tp;
    cudaGetSymbolAddress((void**)&x1p,  g_x1);
    cudaGetSymbolAddress((void**)&aggp, g_agg);
    cudaGetSymbolAddress((void**)&tp,   g_t);

    cudaFuncSetAttribute(gemm128_kernel, cudaFuncAttributeMaxDynamicSharedMemorySize, GEMM_SMEM);

    const int gblocks = (n + 127) / 128;
    const int n4 = n * 32;

    detect_kernel<<<1, 256>>>((const unsigned*)ei, E);
    zero_kernel<<<(n4 + 255) / 256, 256>>>(n4);
    table_kernel<<<TPT, HDIM>>>(mlp0_w, mlp0_b, mlp2_w, mlp2_b);

    gemm128_kernel<<<gblocks, 256, GEMM_SMEM>>>(z, lin1_w, nullptr, nullptr, x1p, n, 0);
    edge_kernel<<<(E + 255) / 256, 256>>>(ei, pos, E);
    gemm128_kernel<<<gblocks, 256, GEMM_SMEM>>>(aggp, lin2_w, lin2_b, nullptr, tp, n, 1);
    gemm128_kernel<<<gblocks, 256, GEMM_SMEM>>>(tp, blk_w, blk_b, z, x1p, n, 2);
    gemm128_kernel<<<gblocks, 256, GEMM_SMEM>>>(x1p, out1_w, out1_b, nullptr, tp, n, 1);
    gemm128_kernel<<<gblocks, 256, GEMM_SMEM>>>(tp, out2_w, out2_b, nullptr, out, n, 0);
}

// round 7
// speedup vs baseline: 1.5387x; 1.5387x over previous
#include <cuda_runtime.h>
#include <cuda_bf16.h>
#include <math.h>

// ---------------- constants ----------------
#define HDIM 128
#define GDIM 51
#define TPT  2048
#define RMAX 1.7330f
#define TAB_H   (RMAX / (float)(TPT - 1))
#define TAB_INVH ((float)(TPT - 1) / RMAX)
#define MAXN 100000

// ---------------- scratch ----------------
__device__ __align__(16) float g_x1 [MAXN * HDIM];
__device__ __align__(16) float g_agg[MAXN * HDIM];
__device__ __align__(16) float g_tab[TPT  * HDIM];
__device__ int g_is64;

__device__ __forceinline__ float sspf(float x) {
    float sp = fmaxf(x, 0.0f) + log1pf(__expf(-fabsf(x)));
    return sp - 0.6931471805599453f;
}

// ---------------- dtype sniff ----------------
__global__ void detect_kernel(const unsigned* __restrict__ ei, int E) {
    __shared__ unsigned red[256];
    unsigned acc = 0;
    int total = 2 * E;
    for (int i = threadIdx.x; i < 2048; i += 256) {
        long long w = 2LL * i + 1;
        if (w < total) acc |= ei[w];
    }
    red[threadIdx.x] = acc;
    __syncthreads();
    for (int s = 128; s > 0; s >>= 1) {
        if (threadIdx.x < s) red[threadIdx.x] |= red[threadIdx.x + s];
        __syncthreads();
    }
    if (threadIdx.x == 0) g_is64 = (red[0] == 0u) ? 1 : 0;
}

// ---------------- zero ----------------
__global__ void zero_kernel(int n4) {
    int i = blockIdx.x * blockDim.x + threadIdx.x;
    if (i < n4) ((float4*)g_agg)[i] = make_float4(0.f, 0.f, 0.f, 0.f);
}

// ---------------- filter table (fp32) ----------------
__global__ void table_kernel(const float* __restrict__ mlp0_w, const float* __restrict__ mlp0_b,
                             const float* __restrict__ mlp2_w, const float* __restrict__ mlp2_b) {
    __shared__ float ea[GDIM];
    __shared__ float hid[HDIM];
    const int f = threadIdx.x;
    const int p = blockIdx.x;
    const float ew = (float)p * TAB_H;

    if (f < GDIM) {
        float off = (float)f * 0.2f;
        float d = ew - off;
        ea[f] = expf(-12.5f * d * d);
    }
    __syncthreads();

    float a = mlp0_b[f];
    #pragma unroll
    for (int g = 0; g < GDIM; ++g)
        a = fmaf(ea[g], mlp0_w[f * GDIM + g], a);
    hid[f] = sspf(a);
    __syncthreads();

    float b = mlp2_b[f];
    #pragma unroll 8
    for (int k = 0; k < HDIM; ++k)
        b = fmaf(hid[k], mlp2_w[f * HDIM + k], b);

    float C = 0.5f * (cosf(ew * 0.31415926535897931f) + 1.0f);
    g_tab[p * HDIM + f] = b * C;
}

// ---------------- edge kernel (R5 exact) ----------------
__global__ __launch_bounds__(256) void edge_kernel(const void* __restrict__ ei_raw,
                                                   const float* __restrict__ pos, int E) {
    const int lane = threadIdx.x & 31;
    const int warp = threadIdx.x >> 5;
    const int base = (blockIdx.x * 8 + warp) * 32;
    if (base >= E) return;

    const int is64 = g_is64;

    int r = 0, c = 0, i0 = 0; float fr = 0.f;
    const int e = base + lane;
    if (e < E) {
        if (is64) {
            const long long* ei = (const long long*)ei_raw;
            r = (int)ei[e];
            c = (int)ei[(size_t)E + e];
        } else {
            const int* ei = (const int*)ei_raw;
            r = ei[e];
            c = ei[(size_t)E + e];
        }
        float ax = __ldg(pos + 3 * r), ay = __ldg(pos + 3 * r + 1), az = __ldg(pos + 3 * r + 2);
        float bx = __ldg(pos + 3 * c), by = __ldg(pos + 3 * c + 1), bz = __ldg(pos + 3 * c + 2);
        float dx = ax - bx, dy = ay - by, dz = az - bz;
        float ew = sqrtf(fmaf(dx, dx, fmaf(dy, dy, fmaf(dz, dz, 1e-12f))));
        float t = ew * TAB_INVH;
        i0 = (int)t;
        if (i0 > TPT - 2) i0 = TPT - 2;
        fr = t - (float)i0;
    }

    int nv = E - base; if (nv > 32) nv = 32;
    for (int j = 0; j < nv; ++j) {
        int   rr = __shfl_sync(0xffffffffu, r,  j);
        int   cc = __shfl_sync(0xffffffffu, c,  j);
        int   ii = __shfl_sync(0xffffffffu, i0, j);
        float ff = __shfl_sync(0xffffffffu, fr, j);

        float4 xv = __ldg((const float4*)g_x1  + (size_t)rr * 32 + lane);
        float4 w0 = __ldg((const float4*)g_tab + (size_t)ii * 32 + lane);
        float4 w1 = __ldg((const float4*)g_tab + (size_t)(ii + 1) * 32 + lane);

        float wx = fmaf(ff, w1.x - w0.x, w0.x);
        float wy = fmaf(ff, w1.y - w0.y, w0.y);
        float wz = fmaf(ff, w1.z - w0.z, w0.z);
        float ww = fmaf(ff, w1.w - w0.w, w0.w);

        float m0 = xv.x * wx, m1 = xv.y * wy, m2 = xv.z * wz, m3 = xv.w * ww;

        float* p = g_agg + (size_t)cc * HDIM + lane * 4;
        asm volatile("red.global.add.v4.f32 [%0], {%1, %2, %3, %4};"
                     :: "l"(p), "f"(m0), "f"(m1), "f"(m2), "f"(m3) : "memory");
    }
}

// ---------------- fused multi-stage GEMM ----------------
// Per 256-row tile: X tile in smem; per stage reload W (permuted) into smem,
// compute Y = ssp?(X @ W^T + b) (+ residual), write back in place (or to gY on
// the final stage). 512 threads, 1 CTA/SM. FFMA2 accumulators.
struct Stages {
    const float* W[4];
    const float* bias[4];
    const float* res[4];   // residual pointer or null
    int flags[4];          // bit0 = ssp
    int count;
};

#define FUSED_SMEM ((128 * 128 + 256 * 128) * 4)   // 64KB ws + 128KB xs = 192KB

__global__ __launch_bounds__(512, 1) void fused_kernel(
    const float* __restrict__ X, float* __restrict__ Y, Stages st, int n)
{
    extern __shared__ float sm[];
    float* ws = sm;                 // permuted [k][128]
    float* xs = sm + 128 * 128;     // [256][128]

    const int tid  = threadIdx.x;
    const int row0 = blockIdx.x << 8;            // 256 rows per tile
    const int tx = tid & 15, ty = tid >> 4;      // ty 0..31

    // ---- load X tile (clamped rows) ----
    {
        const float4* X4 = (const float4*)X;
        #pragma unroll
        for (int it = 0; it < 16; ++it) {
            int idx = tid + it * 512;            // 0..8191
            int r = idx >> 5, kq = idx & 31;
            int gr = row0 + r; if (gr > n - 1) gr = n - 1;
            *(float4*)(xs + r * 128 + kq * 4) = __ldg(X4 + (size_t)gr * 32 + kq);
        }
    }

    for (int s = 0; s < st.count; ++s) {
        const float* W = st.W[s];
        // ---- stage W into permuted smem layout ----
        #pragma unroll
        for (int it = 0; it < 8; ++it) {
            int idx = tid + it * 512;            // 0..4095
            int o = idx & 127, kq = idx >> 7;    // kq 0..31
            float4 v = __ldg((const float4*)W + o * 32 + kq);
            int t = o >> 3, half = (o >> 2) & 1, j = o & 3;
            int base = half * 64 + t * 4 + j;
            ws[(kq * 4 + 0) * 128 + base] = v.x;
            ws[(kq * 4 + 1) * 128 + base] = v.y;
            ws[(kq * 4 + 2) * 128 + base] = v.z;
            ws[(kq * 4 + 3) * 128 + base] = v.w;
        }
        __syncthreads();

        // ---- compute: 8 rows (ty*8..+7) x 8 cols (tx*8..+7) per thread ----
        unsigned long long acc[8][4];
        #pragma unroll
        for (int i = 0; i < 8; ++i)
            #pragma unroll
            for (int m = 0; m < 4; ++m) acc[i][m] = 0ull;

        #pragma unroll 8
        for (int kb = 0; kb < 32; ++kb) {        // 4 k per iter
            float4 xv[8];
            #pragma unroll
            for (int i = 0; i < 8; ++i)
                xv[i] = *(const float4*)(xs + (ty * 8 + i) * 128 + kb * 4);

            #pragma unroll
            for (int dk = 0; dk < 4; ++dk) {
                const int k = kb * 4 + dk;
                ulonglong2 wa = *(const ulonglong2*)(ws + (k << 7) + (tx << 2));
                ulonglong2 wb = *(const ulonglong2*)(ws + (k << 7) + 64 + (tx << 2));
                #pragma unroll
                for (int i = 0; i < 8; ++i) {
                    float xsv = (dk == 0) ? xv[i].x : (dk == 1) ? xv[i].y
                              : (dk == 2) ? xv[i].z : xv[i].w;
                    unsigned xu = __float_as_uint(xsv);
                    unsigned long long x2;
                    asm("mov.b64 %0, {%1, %1};" : "=l"(x2) : "r"(xu));
                    asm("fma.rn.f32x2 %0, %1, %2, %0;" : "+l"(acc[i][0]) : "l"(x2), "l"(wa.x));
                    asm("fma.rn.f32x2 %0, %1, %2, %0;" : "+l"(acc[i][1]) : "l"(x2), "l"(wa.y));
                    asm("fma.rn.f32x2 %0, %1, %2, %0;" : "+l"(acc[i][2]) : "l"(x2), "l"(wb.x));
                    asm("fma.rn.f32x2 %0, %1, %2, %0;" : "+l"(acc[i][3]) : "l"(x2), "l"(wb.y));
                }
            }
        }
        __syncthreads();   // all reads of xs/ws done before overwrite

        // ---- epilogue ----
        const float* bias = st.bias[s];
        const float* res  = st.res[s];
        const int flags   = st.flags[s];
        const int col = tx << 3;
        float4 b0 = make_float4(0.f, 0.f, 0.f, 0.f), b1 = b0;
        if (bias) {
            b0 = __ldg((const float4*)bias + tx * 2);
            b1 = __ldg((const float4*)bias + tx * 2 + 1);
        }
        const bool last = (s == st.count - 1);
        #pragma unroll
        for (int i = 0; i < 8; ++i) {
            int lr = ty * 8 + i;
            int r = row0 + lr;
            float2 p0 = *(float2*)&acc[i][0];
            float2 p1 = *(float2*)&acc[i][1];
            float2 p2 = *(float2*)&acc[i][2];
            float2 p3 = *(float2*)&acc[i][3];
            float4 v0 = make_float4(p0.x + b0.x, p0.y + b0.y, p1.x + b0.z, p1.y + b0.w);
            float4 v1 = make_float4(p2.x + b1.x, p2.y + b1.y, p3.x + b1.z, p3.y + b1.w);
            if (flags & 1) {
                v0.x = sspf(v0.x); v0.y = sspf(v0.y); v0.z = sspf(v0.z); v0.w = sspf(v0.w);
                v1.x = sspf(v1.x); v1.y = sspf(v1.y); v1.z = sspf(v1.z); v1.w = sspf(v1.w);
            }
            if (res) {
                int gr = r > n - 1 ? n - 1 : r;
                float4 r0 = __ldg((const float4*)(res + (size_t)gr * HDIM + col));
                float4 r1 = __ldg((const float4*)(res + (size_t)gr * HDIM + col + 4));
                v0.x += r0.x; v0.y += r0.y; v0.z += r0.z; v0.w += r0.w;
                v1.x += r1.x; v1.y += r1.y; v1.z += r1.z; v1.w += r1.w;
            }
            if (last) {
                if (r < n) {
                    *(float4*)(Y + (size_t)r * HDIM + col)     = v0;
                    *(float4*)(Y + (size_t)r * HDIM + col + 4) = v1;
                }
            } else {
                *(float4*)(xs + lr * 128 + col)     = v0;
                *(float4*)(xs + lr * 128 + col + 4) = v1;
            }
        }
        __syncthreads();   // xs writes visible before next stage's compute
    }
}

// ---------------- launch ----------------
extern "C" void kernel_launch(void* const* d_in, const int* in_sizes, int n_in,
                              void* d_out, int out_size) {
    const float* z      = (const float*)d_in[0];
    const float* pos    = (const float*)d_in[1];
    const void*  ei     = d_in[2];
    const float* lin1_w = (const float*)d_in[3];
    const float* lin2_w = (const float*)d_in[4];
    const float* lin2_b = (const float*)d_in[5];
    const float* mlp0_w = (const float*)d_in[6];
    const float* mlp0_b = (const float*)d_in[7];
    const float* mlp2_w = (const float*)d_in[8];
    const float* mlp2_b = (const float*)d_in[9];
    const float* blk_w  = (const float*)d_in[10];
    const float* blk_b  = (const float*)d_in[11];
    const float* out1_w = (const float*)d_in[12];
    const float* out1_b = (const float*)d_in[13];
    const float* out2_w = (const float*)d_in[14];
    const float* out2_b = (const float*)d_in[15];
    float* out = (float*)d_out;

    const int n = in_sizes[0] / HDIM;
    const int E = in_sizes[2] / 2;

    float *x1p, *aggp;
    cudaGetSymbolAddress((void**)&x1p,  g_x1);
    cudaGetSymbolAddress((void**)&aggp, g_agg);

    cudaFuncSetAttribute(fused_kernel, cudaFuncAttributeMaxDynamicSharedMemorySize, FUSED_SMEM);

    const int fblocks = (n + 255) / 256;
    const int n4 = n * 32;

    detect_kernel<<<1, 256>>>((const unsigned*)ei, E);
    zero_kernel<<<(n4 + 255) / 256, 256>>>(n4);
    table_kernel<<<TPT, HDIM>>>(mlp0_w, mlp0_b, mlp2_w, mlp2_b);

    // x1 = z @ lin1^T  (single stage)
    Stages s1 = {};
    s1.W[0] = lin1_w; s1.bias[0] = nullptr; s1.res[0] = nullptr; s1.flags[0] = 0;
    s1.count = 1;
    fused_kernel<<<fblocks, 512, FUSED_SMEM>>>(z, x1p, s1, n);

    // scatter: agg[col] += x1[row] * lerp(tab, ew)
    edge_kernel<<<(E + 255) / 256, 256>>>(ei, pos, E);

    // fused tail: t=ssp(agg@lin2+b); h=z+t@blk+b; t2=ssp(h@out1+b); out=t2@out2+b
    Stages s2 = {};
    s2.W[0] = lin2_w; s2.bias[0] = lin2_b; s2.res[0] = nullptr; s2.flags[0] = 1;
    s2.W[1] = blk_w;  s2.bias[1] = blk_b;  s2.res[1] = z;       s2.flags[1] = 0;
    s2.W[2] = out1_w; s2.bias[2] = out1_b; s2.res[2] = nullptr; s2.flags[2] = 1;
    s2.W[3] = out2_w; s2.bias[3] = out2_b; s2.res[3] = nullptr; s2.flags[3] = 0;
    s2.count = 4;
    fused_kernel<<<fblocks, 512, FUSED_SMEM>>>(aggp, out, s2, n);
}